// round 7
// baseline (speedup 1.0000x reference)
#include <cuda_runtime.h>
#include <cuda_bf16.h>
#include <cstdint>

// SeparationLoss: mean over B of sum_{i!=j} max(0, thr2 - ||kp_i - kp_j||^2)
// Input: batched_kps [B, 17, 3] f32 (B = 131072). Output: scalar f32.
//
// R7: role split (A: joints 0-7, B: joints 8-16) x f32x2 packing (2 rows per
// thread). fma.rn.f32x2 halves fma-pipe ops/row (the measured rt=2 fma-pipe
// throughput wall); FMNMX + pack go to the idle alu pipe. Cross pairs loop-
// interchanged: foreign joint loaded once (LDS 2.6x down vs R6). Bulk-copy
// staging + fused last-block-done reduction retained.

#define J 17
#define ROW_F 51                    // 17*3 floats per row
#define ROWS_PER_BLOCK 128          // 64 packed row-pairs
#define THREADS 128                 // 64 A-threads (warps 0-1) + 64 B (warps 2-3)
#define TILE_BYTES (ROWS_PER_BLOCK * ROW_F * 4)   // 26112
#define NBLOCKS_MAX 8192
#define XSPLIT 39                   // cross pair c = i*9+jj: c<39 -> A, else B

__device__ __align__(16) float g_partials[NBLOCKS_MAX];
__device__ unsigned int g_done_count;   // zero-init; atomicInc wrap self-resets

typedef unsigned long long u64;

__device__ __forceinline__ uint32_t smem_u32(const void* p) {
    uint32_t a;
    asm("{ .reg .u64 t; cvta.to.shared.u64 t, %1; cvt.u32.u64 %0, t; }"
        : "=r"(a) : "l"(p));
    return a;
}
__device__ __forceinline__ u64 pack2(float lo, float hi) {
    u64 r; asm("mov.b64 %0, {%1, %2};" : "=l"(r) : "f"(lo), "f"(hi)); return r;
}
__device__ __forceinline__ void unpack2(u64 v, float& lo, float& hi) {
    asm("mov.b64 {%0, %1}, %2;" : "=f"(lo), "=f"(hi) : "l"(v));
}
__device__ __forceinline__ u64 fma2(u64 a, u64 b, u64 c) {
    u64 d; asm("fma.rn.f32x2 %0, %1, %2, %3;" : "=l"(d) : "l"(a), "l"(b), "l"(c));
    return d;
}
__device__ __forceinline__ u64 add2(u64 a, u64 b) {
    u64 d; asm("add.rn.f32x2 %0, %1, %2;" : "=l"(d) : "l"(a), "l"(b));
    return d;
}

// one pair, two rows at once (lo/hi lanes of each u64)
#define PAIR2(PX, PY, PZ, QX, QY, QZ)                                   \
    {                                                                   \
        u64 dx = fma2((QX), neg1, (PX));                                \
        u64 dy = fma2((QY), neg1, (PY));                                \
        u64 dz = fma2((QZ), neg1, (PZ));                                \
        u64 t  = fma2(dx, dx, fma2(dy, dy, fma2(dz, dz, mthr2)));       \
        float tl, th; unpack2(t, tl, th);                               \
        float hl = fmaxf(-tl, 0.0f), hh = fmaxf(-th, 0.0f);             \
        if (k & 1) acc1 = add2(acc1, pack2(hl, hh));                    \
        else       acc0 = add2(acc0, pack2(hl, hh));                    \
        k++;                                                            \
    }

__global__ __launch_bounds__(THREADS, 6)   // 85-reg cap; ~74 expected, no spill
void sep_loss_fused(const float* __restrict__ kps, int B, int nblocks,
                    float invB, float* __restrict__ out) {
    __shared__ __align__(16) float s[ROWS_PER_BLOCK * ROW_F];   // 26112 B
    __shared__ __align__(8)  unsigned long long mbar;
    __shared__ float wsum[THREADS / 32];
    __shared__ bool  isLast;

    const int tid = threadIdx.x;
    const int rowBase = blockIdx.x * ROWS_PER_BLOCK;
    const int rowsHere = min(ROWS_PER_BLOCK, B - rowBase);

    if (rowsHere == ROWS_PER_BLOCK) {
        const uint32_t mb = smem_u32(&mbar);
        if (tid == 0)
            asm volatile("mbarrier.init.shared.b64 [%0], %1;"
                         :: "r"(mb), "r"(1) : "memory");
        __syncthreads();
        if (tid == 0) {
            asm volatile("mbarrier.arrive.expect_tx.shared.b64 _, [%0], %1;"
                         :: "r"(mb), "r"((uint32_t)TILE_BYTES) : "memory");
            asm volatile(
                "cp.async.bulk.shared::cta.global.mbarrier::complete_tx::bytes "
                "[%0], [%1], %2, [%3];"
                :: "r"(smem_u32(s)), "l"(kps + (size_t)rowBase * ROW_F),
                   "r"((uint32_t)TILE_BYTES), "r"(mb)
                : "memory");
        }
        uint32_t done;
        asm volatile(
            "{\n\t.reg .pred p;\n\t"
            "mbarrier.try_wait.parity.acquire.cta.shared::cta.b64 p, [%1], %2;\n\t"
            "selp.b32 %0, 1, 0, p;\n\t}"
            : "=r"(done) : "r"(mb), "r"(0u) : "memory");
        if (!done) {
            asm volatile(
                "{\n\t.reg .pred P1;\n\t"
                "W_%=:\n\t"
                "mbarrier.try_wait.parity.acquire.cta.shared::cta.b64 P1, [%0], %1, 0x989680;\n\t"
                "@P1 bra.uni D_%=;\n\t"
                "bra.uni W_%=;\n\t"
                "D_%=:\n\t}"
                :: "r"(mb), "r"(0u) : "memory");
        }
    } else {
        const int n = rowsHere * ROW_F;
        const float* src = kps + (size_t)rowBase * ROW_F;
        for (int i = tid; i < n; i += THREADS) s[i] = src[i];
        __syncthreads();
    }

    // ---- roles: warps 0-1 = A (joints 0-7), warps 2-3 = B (joints 8-16) ----
    const bool roleA = tid < 64;
    const int t = roleA ? tid : (tid - 64);
    const int r0 = 2 * t, r1 = 2 * t + 1;
    const bool v0 = r0 < rowsHere, v1 = r1 < rowsHere;
    const float* __restrict__ rp0 = s + (v0 ? r0 : 0) * ROW_F;
    const float* __restrict__ rp1 = s + (v1 ? r1 : 0) * ROW_F;

    const u64 neg1  = pack2(-1.0f, -1.0f);
    const u64 mthr2 = pack2(-0.01f, -0.01f);
    u64 acc0 = 0, acc1 = 0;
    int k = 0;

    if (roleA) {
        u64 p[24];                               // joints 0..7, both rows
        #pragma unroll
        for (int c = 0; c < 24; c++) p[c] = pack2(rp0[c], rp1[c]);
        // intra-A: 28 pairs, register-only
        #pragma unroll
        for (int i = 0; i < 8; i++)
            #pragma unroll
            for (int j = i + 1; j < 8; j++)
                PAIR2(p[3*i], p[3*i+1], p[3*i+2], p[3*j], p[3*j+1], p[3*j+2]);
        // cross (interchanged: foreign B-joint jj outer, loaded once)
        #pragma unroll
        for (int jj = 0; jj < 9; jj++) {
            u64 fx = pack2(rp0[24 + 3*jj],     rp1[24 + 3*jj]);
            u64 fy = pack2(rp0[24 + 3*jj + 1], rp1[24 + 3*jj + 1]);
            u64 fz = pack2(rp0[24 + 3*jj + 2], rp1[24 + 3*jj + 2]);
            #pragma unroll
            for (int i = 0; i < 8; i++)
                if (i * 9 + jj < XSPLIT)
                    PAIR2(p[3*i], p[3*i+1], p[3*i+2], fx, fy, fz);
        }
    } else {
        u64 p[27];                               // joints 8..16, both rows
        #pragma unroll
        for (int c = 0; c < 27; c++) p[c] = pack2(rp0[24 + c], rp1[24 + c]);
        // intra-B: 36 pairs, register-only
        #pragma unroll
        for (int i = 0; i < 9; i++)
            #pragma unroll
            for (int j = i + 1; j < 9; j++)
                PAIR2(p[3*i], p[3*i+1], p[3*i+2], p[3*j], p[3*j+1], p[3*j+2]);
        // cross (interchanged: foreign A-joint i outer, loaded once)
        #pragma unroll
        for (int i = 0; i < 8; i++) {
            u64 fx = pack2(rp0[3*i],     rp1[3*i]);
            u64 fy = pack2(rp0[3*i + 1], rp1[3*i + 1]);
            u64 fz = pack2(rp0[3*i + 2], rp1[3*i + 2]);
            #pragma unroll
            for (int jj = 0; jj < 9; jj++)
                if (i * 9 + jj >= XSPLIT)
                    PAIR2(fx, fy, fz, p[3*jj], p[3*jj+1], p[3*jj+2]);
        }
    }

    // ---- unpack, mask invalid rows, x2 for ordered pairs ----
    float l0, h0, l1, h1;
    unpack2(acc0, l0, h0);
    unpack2(acc1, l1, h1);
    float accLo = v0 ? (l0 + l1) : 0.0f;
    float accHi = v1 ? (h0 + h1) : 0.0f;
    float acc = (accLo + accHi) * 2.0f;

    // ---- deterministic block reduction (4 warps) ----
    #pragma unroll
    for (int off = 16; off > 0; off >>= 1)
        acc += __shfl_down_sync(0xFFFFFFFFu, acc, off);
    if ((tid & 31) == 0) wsum[tid >> 5] = acc;
    __syncthreads();

    if (tid == 0) {
        g_partials[blockIdx.x] = (wsum[0] + wsum[1]) + (wsum[2] + wsum[3]);
        __threadfence();
        unsigned int c = atomicInc(&g_done_count, (unsigned int)(nblocks - 1));
        isLast = (c == (unsigned int)(nblocks - 1));
    }
    __syncthreads();

    // ---- last block: vectorized fixed-order final reduction ----
    if (isLast) {
        float v = 0.0f;
        const int nvec = nblocks >> 2;
        const float4* gp = reinterpret_cast<const float4*>(g_partials);
        #pragma unroll 2
        for (int i = tid; i < nvec; i += THREADS) {
            float4 f = gp[i];
            v += (f.x + f.y) + (f.z + f.w);
        }
        for (int i = (nvec << 2) + tid; i < nblocks; i += THREADS)
            v += g_partials[i];
        #pragma unroll
        for (int off = 16; off > 0; off >>= 1)
            v += __shfl_down_sync(0xFFFFFFFFu, v, off);
        if ((tid & 31) == 0) wsum[tid >> 5] = v;
        __syncthreads();
        if (tid == 0)
            out[0] = ((wsum[0] + wsum[1]) + (wsum[2] + wsum[3])) * invB;
    }
}

extern "C" void kernel_launch(void* const* d_in, const int* in_sizes, int n_in,
                              void* d_out, int out_size) {
    const float* kps = (const float*)d_in[0];
    const int B = in_sizes[0] / ROW_F;
    const int nblocks = (B + ROWS_PER_BLOCK - 1) / ROWS_PER_BLOCK;  // 1024

    sep_loss_fused<<<nblocks, THREADS>>>(kps, B, nblocks, 1.0f / (float)B,
                                         (float*)d_out);
}

// round 8
// speedup vs baseline: 1.1604x; 1.1604x over previous
#include <cuda_runtime.h>
#include <cuda_bf16.h>
#include <cstdint>

// SeparationLoss: mean over B of sum_{i!=j} max(0, thr2 - ||kp_i - kp_j||^2)
// Input: batched_kps [B, 17, 3] f32 (B = 131072). Output: scalar f32.
//
// R8: Gram-identity inner loop: thr2 - d2 = 2*(g_i + g_j + dot(p_i,p_j)),
// g = 0.25*thr2 - 0.5*||p||^2 precomputed per joint. 5 fma-class ops/pair vs 7
// (the measured wall is fma-pipe rt=2 throughput). Scalar math only (f32x2
// failed twice: regs in R2, alu-pipe MOVs in R7). Bulk-copy staging + fused
// last-block-done reduction retained.

#define J 17
#define ROW_F 51                    // 17*3 floats per row
#define ROWS_PER_BLOCK 128
#define THREADS 128
#define TILE_BYTES (ROWS_PER_BLOCK * ROW_F * 4)   // 26112
#define NBLOCKS_MAX 8192

__device__ __align__(16) float g_partials[NBLOCKS_MAX];
__device__ unsigned int g_done_count;   // zero-init; atomicInc wrap self-resets

__device__ __forceinline__ uint32_t smem_u32(const void* p) {
    uint32_t a;
    asm("{ .reg .u64 t; cvta.to.shared.u64 t, %1; cvt.u32.u64 %0, t; }"
        : "=r"(a) : "l"(p));
    return a;
}

__global__ __launch_bounds__(THREADS, 6)   // 85-reg cap; ~88 demand, cold spills to idle LSU
void sep_loss_fused(const float* __restrict__ kps, int B, int nblocks,
                    float invB, float* __restrict__ out) {
    __shared__ __align__(16) float s[ROWS_PER_BLOCK * ROW_F];   // 26112 B
    __shared__ __align__(8)  unsigned long long mbar;
    __shared__ float wsum[THREADS / 32];
    __shared__ bool  isLast;

    const int tid = threadIdx.x;
    const int rowBase = blockIdx.x * ROWS_PER_BLOCK;
    const int rowsHere = min(ROWS_PER_BLOCK, B - rowBase);

    if (rowsHere == ROWS_PER_BLOCK) {
        // ---- single bulk copy per block ----
        const uint32_t mb = smem_u32(&mbar);
        if (tid == 0)
            asm volatile("mbarrier.init.shared.b64 [%0], %1;"
                         :: "r"(mb), "r"(1) : "memory");
        __syncthreads();
        if (tid == 0) {
            asm volatile("mbarrier.arrive.expect_tx.shared.b64 _, [%0], %1;"
                         :: "r"(mb), "r"((uint32_t)TILE_BYTES) : "memory");
            asm volatile(
                "cp.async.bulk.shared::cta.global.mbarrier::complete_tx::bytes "
                "[%0], [%1], %2, [%3];"
                :: "r"(smem_u32(s)), "l"(kps + (size_t)rowBase * ROW_F),
                   "r"((uint32_t)TILE_BYTES), "r"(mb)
                : "memory");
        }
        uint32_t done;
        asm volatile(
            "{\n\t.reg .pred p;\n\t"
            "mbarrier.try_wait.parity.acquire.cta.shared::cta.b64 p, [%1], %2;\n\t"
            "selp.b32 %0, 1, 0, p;\n\t}"
            : "=r"(done) : "r"(mb), "r"(0u) : "memory");
        if (!done) {
            asm volatile(
                "{\n\t.reg .pred P1;\n\t"
                "W_%=:\n\t"
                "mbarrier.try_wait.parity.acquire.cta.shared::cta.b64 P1, [%0], %1, 0x989680;\n\t"
                "@P1 bra.uni D_%=;\n\t"
                "bra.uni W_%=;\n\t"
                "D_%=:\n\t}"
                :: "r"(mb), "r"(0u) : "memory");
        }
    } else {
        const int n = rowsHere * ROW_F;
        const float* src = kps + (size_t)rowBase * ROW_F;
        for (int i = tid; i < n; i += THREADS) s[i] = src[i];
        __syncthreads();
    }

    // ---- per-thread row: coords + per-joint g = 0.25*thr2 - 0.5*||p||^2 ----
    float a0 = 0.0f, a1 = 0.0f;
    if (tid < rowsHere) {
        float p[ROW_F];
        float g[J];
        #pragma unroll
        for (int c = 0; c < ROW_F; c++) p[c] = s[tid * ROW_F + c];
        #pragma unroll
        for (int i = 0; i < J; i++) {
            float x = p[3*i], y = p[3*i+1], z = p[3*i+2];
            float r = fmaf(z, z, fmaf(y, y, x * x));
            g[i] = fmaf(r, -0.5f, 0.0025f);     // 0.25 * thr2 ; FFMA-imm (rt=1)
        }

        int k = 0;
        #pragma unroll
        for (int i = 0; i < J; i++) {
            #pragma unroll
            for (int j = i + 1; j < J; j++) {
                // d = 0.5*(thr2 - d2_ij) = g_i + g_j + dot(p_i, p_j)
                float w = g[i] + g[j];
                float d = fmaf(p[3*i+2], p[3*j+2],
                          fmaf(p[3*i+1], p[3*j+1],
                          fmaf(p[3*i  ], p[3*j  ], w)));
                float h = fmaxf(d, 0.0f);        // FMNMX (alu pipe)
                if (k & 1) a1 += h; else a0 += h;
                k++;
            }
        }
    }
    // hinge = 2*max(0,d); ordered pairs double it again -> x4
    float acc = (a0 + a1) * 4.0f;

    // ---- deterministic block reduction (4 warps) ----
    #pragma unroll
    for (int off = 16; off > 0; off >>= 1)
        acc += __shfl_down_sync(0xFFFFFFFFu, acc, off);
    if ((tid & 31) == 0) wsum[tid >> 5] = acc;
    __syncthreads();

    if (tid == 0) {
        g_partials[blockIdx.x] = (wsum[0] + wsum[1]) + (wsum[2] + wsum[3]);
        __threadfence();
        unsigned int c = atomicInc(&g_done_count, (unsigned int)(nblocks - 1));
        isLast = (c == (unsigned int)(nblocks - 1));
    }
    __syncthreads();

    // ---- last block: vectorized fixed-order final reduction ----
    if (isLast) {
        float v = 0.0f;
        const int nvec = nblocks >> 2;          // 256 for nblocks=1024
        const float4* gp = reinterpret_cast<const float4*>(g_partials);
        #pragma unroll 2
        for (int i = tid; i < nvec; i += THREADS) {
            float4 f = gp[i];
            v += (f.x + f.y) + (f.z + f.w);
        }
        for (int i = (nvec << 2) + tid; i < nblocks; i += THREADS)
            v += g_partials[i];
        #pragma unroll
        for (int off = 16; off > 0; off >>= 1)
            v += __shfl_down_sync(0xFFFFFFFFu, v, off);
        if ((tid & 31) == 0) wsum[tid >> 5] = v;
        __syncthreads();
        if (tid == 0)
            out[0] = ((wsum[0] + wsum[1]) + (wsum[2] + wsum[3])) * invB;
    }
}

extern "C" void kernel_launch(void* const* d_in, const int* in_sizes, int n_in,
                              void* d_out, int out_size) {
    const float* kps = (const float*)d_in[0];
    const int B = in_sizes[0] / ROW_F;
    const int nblocks = (B + ROWS_PER_BLOCK - 1) / ROWS_PER_BLOCK;  // 1024

    sep_loss_fused<<<nblocks, THREADS>>>(kps, B, nblocks, 1.0f / (float)B,
                                         (float*)d_out);
}